// round 2
// baseline (speedup 1.0000x reference)
#include <cuda_runtime.h>
#include <math.h>

#define BB 4
#define SS 2048
#define DD 1024
#define GG 512
#define WW 8
#define SDIFF 2047              // diffs per batch
#define ND (BB*SDIFF)           // 8188 total diff rows
#define MT 16                   // diff rows per CTA in main kernel
#define NTILES ((ND + MT - 1)/MT)   // 512

// Scratch (static __device__ — no allocations allowed)
__device__ float d_ginv[GG];
__device__ float d_gT[DD*GG];               // [k][g], guidance transposed & pre-divided by ||g||
__device__ float d_mw[ND];                  // tanh(2*mag) per diff
__device__ float d_blended[8388608];        // [ND][DD] (8188*1024 = 8384512 used)

// ---------------- kernel 0a: inverse guidance norms ----------------
__global__ void k_ginv(const float* __restrict__ guid) {
    int g = blockIdx.x;
    const float4* row = (const float4*)(guid + (size_t)g * DD);
    float4 x = row[threadIdx.x];
    float s = x.x*x.x + x.y*x.y + x.z*x.z + x.w*x.w;
    #pragma unroll
    for (int o = 16; o; o >>= 1) s += __shfl_xor_sync(0xffffffffu, s, o);
    __shared__ float red[8];
    int wid = threadIdx.x >> 5, lane = threadIdx.x & 31;
    if (lane == 0) red[wid] = s;
    __syncthreads();
    if (threadIdx.x == 0) {
        float t = 0.f;
        #pragma unroll
        for (int i = 0; i < 8; i++) t += red[i];
        d_ginv[g] = 1.0f / fmaxf(sqrtf(t), 1e-8f);
    }
}

// ---------------- kernel 0b: transpose guidance with norm folded in ----------------
__global__ void k_gt(const float* __restrict__ guid) {
    __shared__ float tile[32][33];
    int k0 = blockIdx.x * 32;
    int g0 = blockIdx.y * 32;
    int tx = threadIdx.x, ty = threadIdx.y;
    #pragma unroll
    for (int yy = ty; yy < 32; yy += 8)
        tile[yy][tx] = guid[(size_t)(g0 + yy) * DD + (k0 + tx)] * d_ginv[g0 + yy];
    __syncthreads();
    #pragma unroll
    for (int yy = ty; yy < 32; yy += 8)
        d_gT[(size_t)(k0 + yy) * GG + (g0 + tx)] = tile[tx][yy];
}

// ---------------- kernel 1: per-diff normalize -> sims -> softmax -> influence -> blended ----------------
__global__ void __launch_bounds__(256, 2) k_main(
        const float* __restrict__ emb, const float* __restrict__ guid) {
    extern __shared__ float sm[];
    float* s_normed = sm;            // [MT][DD]  64KB
    float* s_w      = sm + MT * DD;  // [MT][GG]  32KB
    int tid  = threadIdx.x;
    int lane = tid & 31, wid = tid >> 5;
    int tile = blockIdx.x;

    // ---- Phase 1: diffs, magnitude, normalize into shared ----
    #pragma unroll
    for (int mm = 0; mm < 2; mm++) {
        int m = wid + 8 * mm;
        int r = tile * MT + m;
        float4 df[8];
        float ssq = 0.f;
        if (r < ND) {
            int b = r / SDIFF;
            int i = r - b * SDIFF;
            const float4* e0 = (const float4*)(emb + ((size_t)b * SS + i) * DD);
            #pragma unroll
            for (int it = 0; it < 8; it++) {
                int v = lane + 32 * it;
                float4 a = e0[v + DD/4];
                float4 c = e0[v];
                df[it].x = a.x - c.x; df[it].y = a.y - c.y;
                df[it].z = a.z - c.z; df[it].w = a.w - c.w;
                ssq += df[it].x*df[it].x + df[it].y*df[it].y
                     + df[it].z*df[it].z + df[it].w*df[it].w;
            }
        } else {
            #pragma unroll
            for (int it = 0; it < 8; it++) df[it] = make_float4(0.f,0.f,0.f,0.f);
        }
        #pragma unroll
        for (int o = 16; o; o >>= 1) ssq += __shfl_xor_sync(0xffffffffu, ssq, o);
        float mag = sqrtf(ssq);
        float scale = (mag > 1e-6f) ? (1.0f / mag) : 0.0f;
        if (r < ND && lane == 0) d_mw[r] = tanhf(2.0f * mag);
        float4* srow = (float4*)(s_normed + m * DD);
        #pragma unroll
        for (int it = 0; it < 8; it++) {
            float4 o4;
            o4.x = df[it].x * scale; o4.y = df[it].y * scale;
            o4.z = df[it].z * scale; o4.w = df[it].w * scale;
            srow[lane + 32 * it] = o4;
        }
    }
    __syncthreads();

    // ---- Phase 2: sims[m][g] = normed[m] . gT[:,g]  (g = 2*tid, 2*tid+1) ----
    float acc[MT][2];
    #pragma unroll
    for (int m = 0; m < MT; m++) { acc[m][0] = 0.f; acc[m][1] = 0.f; }
    const float2* gT2 = (const float2*)d_gT;   // float2 over g; index k*(GG/2)+tid
    #pragma unroll 1
    for (int k4 = 0; k4 < DD; k4 += 4) {
        float2 gv0 = gT2[(size_t)(k4 + 0) * (GG/2) + tid];
        float2 gv1 = gT2[(size_t)(k4 + 1) * (GG/2) + tid];
        float2 gv2 = gT2[(size_t)(k4 + 2) * (GG/2) + tid];
        float2 gv3 = gT2[(size_t)(k4 + 3) * (GG/2) + tid];
        #pragma unroll
        for (int m = 0; m < MT; m++) {
            float4 nm = *(const float4*)(s_normed + m * DD + k4);
            acc[m][0] = fmaf(nm.x, gv0.x, acc[m][0]);
            acc[m][0] = fmaf(nm.y, gv1.x, acc[m][0]);
            acc[m][0] = fmaf(nm.z, gv2.x, acc[m][0]);
            acc[m][0] = fmaf(nm.w, gv3.x, acc[m][0]);
            acc[m][1] = fmaf(nm.x, gv0.y, acc[m][1]);
            acc[m][1] = fmaf(nm.y, gv1.y, acc[m][1]);
            acc[m][1] = fmaf(nm.z, gv2.y, acc[m][1]);
            acc[m][1] = fmaf(nm.w, gv3.y, acc[m][1]);
        }
    }
    #pragma unroll
    for (int m = 0; m < MT; m++)
        *(float2*)(s_w + m * GG + 2 * tid) = make_float2(acc[m][0], acc[m][1]);
    __syncthreads();

    // ---- Phase 3: softmax over g (temperature 2), one warp per 2 rows ----
    #pragma unroll
    for (int mm = 0; mm < 2; mm++) {
        int m = wid + 8 * mm;
        float* row = s_w + m * GG;
        float mx = -1e30f;
        for (int j = lane; j < GG; j += 32) mx = fmaxf(mx, row[j]);
        #pragma unroll
        for (int o = 16; o; o >>= 1) mx = fmaxf(mx, __shfl_xor_sync(0xffffffffu, mx, o));
        float sum = 0.f;
        for (int j = lane; j < GG; j += 32) {
            float e = expf(2.0f * (row[j] - mx));
            row[j] = e;
            sum += e;
        }
        #pragma unroll
        for (int o = 16; o; o >>= 1) sum += __shfl_xor_sync(0xffffffffu, sum, o);
        float inv = 1.0f / sum;
        for (int j = lane; j < GG; j += 32) row[j] *= inv;
    }
    __syncthreads();

    // ---- Phase 4: influence[m][d] = sum_g w[m][g]*guid[g][d]; blend; store ----
    float fa[MT][4];
    #pragma unroll
    for (int m = 0; m < MT; m++) {
        fa[m][0] = 0.f; fa[m][1] = 0.f; fa[m][2] = 0.f; fa[m][3] = 0.f;
    }
    const float4* gp = (const float4*)guid;   // [g][DD/4], thread owns d = 4*tid..4*tid+3
    #pragma unroll 2
    for (int g = 0; g < GG; g++) {
        float4 gv = gp[(size_t)g * (DD/4) + tid];
        #pragma unroll
        for (int m = 0; m < MT; m++) {
            float w = s_w[m * GG + g];
            fa[m][0] = fmaf(w, gv.x, fa[m][0]);
            fa[m][1] = fmaf(w, gv.y, fa[m][1]);
            fa[m][2] = fmaf(w, gv.z, fa[m][2]);
            fa[m][3] = fmaf(w, gv.w, fa[m][3]);
        }
    }
    int d0 = tid * 4;
    #pragma unroll
    for (int m = 0; m < MT; m++) {
        int r = tile * MT + m;
        if (r < ND) {
            float4 nm = *(const float4*)(s_normed + m * DD + d0);
            float4 o;
            o.x = 0.6f * nm.x + 0.4f * fa[m][0];
            o.y = 0.6f * nm.y + 0.4f * fa[m][1];
            o.z = 0.6f * nm.z + 0.4f * fa[m][2];
            o.w = 0.6f * nm.w + 0.4f * fa[m][3];
            *(float4*)(d_blended + (size_t)r * DD + d0) = o;
        }
    }
}

// ---------------- kernel 2: windowed weighted blend into output ----------------
__global__ void __launch_bounds__(256) k_out(float* __restrict__ out) {
    int pos = blockIdx.x;            // 0 .. B*S-1
    int b = pos >> 11;               // / 2048
    int p = pos & (SS - 1);
    int base = b * SDIFF;
    float c[WW];
    float wsum = 0.f;
    #pragma unroll
    for (int k = 0; k < WW; k++) {
        int idx = p - WW + k;
        float ck = 0.f;
        if (p >= 1 && idx >= 0) {
            int w = (p < WW) ? p : WW;
            int j = k - (WW - w);
            float lin = (w > 1) ? (0.1f + 0.9f * (float)j / (float)(w - 1)) : 0.1f;
            ck = lin * d_mw[base + idx];
        }
        c[k] = ck;
        wsum += ck;
    }
    float inv = 1.0f / fmaxf(wsum, 1e-8f);
    int d4 = threadIdx.x;            // float4 index, 256 per row
    float4 o = make_float4(0.f, 0.f, 0.f, 0.f);
    #pragma unroll
    for (int k = 0; k < WW; k++) {
        int idx = p - WW + k;
        if (c[k] != 0.f) {
            float4 v = *(const float4*)(d_blended + (size_t)(base + idx) * DD + d4 * 4);
            o.x = fmaf(c[k], v.x, o.x);
            o.y = fmaf(c[k], v.y, o.y);
            o.z = fmaf(c[k], v.z, o.z);
            o.w = fmaf(c[k], v.w, o.w);
        }
    }
    o.x *= inv; o.y *= inv; o.z *= inv; o.w *= inv;
    ((float4*)out)[(size_t)pos * (DD/4) + d4] = o;
}

extern "C" void kernel_launch(void* const* d_in, const int* in_sizes, int n_in,
                              void* d_out, int out_size) {
    (void)in_sizes; (void)n_in; (void)out_size;
    const float* emb  = (const float*)d_in[0];   // (4, 2048, 1024) f32
    const float* guid = (const float*)d_in[1];   // (512, 1024)     f32
    float* out = (float*)d_out;                  // (4, 2048, 1024) f32

    const int smem = (MT * DD + MT * GG) * (int)sizeof(float);  // 98304
    cudaFuncSetAttribute(k_main, cudaFuncAttributeMaxDynamicSharedMemorySize, smem);

    k_ginv<<<GG, 256>>>(guid);
    k_gt<<<dim3(DD/32, GG/32), dim3(32, 8)>>>(guid);
    k_main<<<NTILES, 256, smem>>>(emb, guid);
    k_out<<<BB * SS, 256>>>(out);
}